// round 3
// baseline (speedup 1.0000x reference)
#include <cuda_runtime.h>
#include <cstdint>

#define EDIM 1024
#define HD_  64
#define HH_  16
#define TT_  1024
#define BB_  2
#define LL_  4
#define FF_  4096
#define VV_  32000
#define MROWS (BB_*TT_)   // 2048
#define BHN  (BB_*HH_)    // 32

// ---------------- scratch (static device memory; no allocs) ----------------
__device__ float g_x   [MROWS*EDIM];
__device__ float g_z   [MROWS*EDIM];
__device__ float g_z2  [MROWS*EDIM];
__device__ float g_q   [MROWS*EDIM];
__device__ float g_k   [MROWS*EDIM];
__device__ float g_v   [MROWS*EDIM];
__device__ float g_attn[MROWS*EDIM];
__device__ float g_h   [MROWS*FF_];
__device__ int   g_tok64;

// ---------------- helpers ----------------
__device__ __forceinline__ float blockReduceSum(float v, float* sh) {
    __syncthreads();
    #pragma unroll
    for (int o = 16; o; o >>= 1) v += __shfl_xor_sync(0xffffffffu, v, o);
    if ((threadIdx.x & 31) == 0) sh[threadIdx.x >> 5] = v;
    __syncthreads();
    int nw = blockDim.x >> 5;
    float t = (threadIdx.x < (unsigned)nw) ? sh[threadIdx.x] : 0.f;
    if (threadIdx.x < 32) {
        #pragma unroll
        for (int o = 16; o; o >>= 1) t += __shfl_xor_sync(0xffffffffu, t, o);
        if (threadIdx.x == 0) sh[0] = t;
    }
    __syncthreads();
    return sh[0];
}

// ---------------- token dtype detect (int64 vs int32) ----------------
__global__ void detect_kernel(const int* __restrict__ tok) {
    __shared__ int nz;
    if (threadIdx.x == 0) nz = 0;
    __syncthreads();
    int c = 0;
    for (int j = threadIdx.x; j < 1024; j += blockDim.x)
        if (tok[2*j + 1] != 0) c++;
    if (c) atomicAdd(&nz, c);
    __syncthreads();
    if (threadIdx.x == 0) g_tok64 = (nz == 0) ? 1 : 0;
}

// ---------------- embedding + positional encoding ----------------
__global__ __launch_bounds__(256) void embed_kernel(const void* __restrict__ tokp,
                                                    const float* __restrict__ emb,
                                                    float* __restrict__ X) {
    int row = blockIdx.x;            // b*T + t
    int t   = row & (TT_ - 1);
    int token;
    if (g_tok64) token = (int)((const long long*)tokp)[row];
    else         token = ((const int*)tokp)[row];
    int e = threadIdx.x * 4;
    float4 v = *(const float4*)(emb + (size_t)token * EDIM + e);
    double i0 = (double)(e >> 1);
    double i1 = i0 + 1.0;
    double d0 = pow(10000.0, 2.0 * i0 / (double)EDIM);
    double d1 = pow(10000.0, 2.0 * i1 / (double)EDIM);
    double a0 = (double)t / d0;
    double a1 = (double)t / d1;
    v.x += (float)sin(a0); v.y += (float)cos(a0);
    v.z += (float)sin(a1); v.w += (float)cos(a1);
    *(float4*)(X + (size_t)row * EDIM + e) = v;
}

// ---------------- layernorm (row = 1024) ----------------
__global__ __launch_bounds__(256) void ln_kernel(const float* __restrict__ X,
                                                 const float* __restrict__ g,
                                                 const float* __restrict__ b,
                                                 float* __restrict__ Y) {
    __shared__ float sh[32];
    int row = blockIdx.x;
    int e = threadIdx.x * 4;
    const float* xr = X + (size_t)row * EDIM;
    float4 v = *(const float4*)(xr + e);
    float mean = blockReduceSum(v.x + v.y + v.z + v.w, sh) * (1.f / EDIM);
    float dx = v.x - mean, dy = v.y - mean, dz = v.z - mean, dw = v.w - mean;
    float var = blockReduceSum(dx*dx + dy*dy + dz*dz + dw*dw, sh) * (1.f / EDIM);
    float r = rsqrtf(var + 1e-5f);
    float4 gg = *(const float4*)(g + e);
    float4 bb = *(const float4*)(b + e);
    float4 o;
    o.x = dx * r * gg.x + bb.x;
    o.y = dy * r * gg.y + bb.y;
    o.z = dz * r * gg.z + bb.z;
    o.w = dw * r * gg.w + bb.w;
    *(float4*)(Y + (size_t)row * EDIM + e) = o;
}

// ---------------- SGEMM: C = A[MxK] @ W[KxN] (+bias)(+res)(relu) ------------
__global__ __launch_bounds__(256) void sgemm_kernel(const float* __restrict__ A,
                                                    const float* __restrict__ Wt,
                                                    const float* __restrict__ bias,
                                                    const float* __restrict__ res,
                                                    float* __restrict__ C,
                                                    int M, int N, int K, int relu) {
    __shared__ float As[8][128];
    __shared__ float Bs[8][128];
    const int tid = threadIdx.x;
    const int bm = blockIdx.y * 128, bn = blockIdx.x * 128;
    const int tx = tid & 15, ty = tid >> 4;
    const int arow = tid >> 1, acol = (tid & 1) * 4;
    const int brow = tid >> 5, bcol = (tid & 31) * 4;
    const float* Aptr = A + (size_t)(bm + arow) * K + acol;
    const float* Bptr = Wt + (size_t)brow * N + bn + bcol;
    float acc[8][8];
    #pragma unroll
    for (int i = 0; i < 8; i++)
        #pragma unroll
        for (int j = 0; j < 8; j++) acc[i][j] = 0.f;

    for (int k0 = 0; k0 < K; k0 += 8) {
        float4 av = *(const float4*)(Aptr + k0);
        float4 bv = *(const float4*)(Bptr + (size_t)k0 * N);
        As[acol + 0][arow] = av.x;
        As[acol + 1][arow] = av.y;
        As[acol + 2][arow] = av.z;
        As[acol + 3][arow] = av.w;
        *(float4*)&Bs[brow][bcol] = bv;
        __syncthreads();
        #pragma unroll
        for (int kk = 0; kk < 8; kk++) {
            float a[8], b[8];
            *(float4*)(a)     = *(float4*)&As[kk][ty * 8];
            *(float4*)(a + 4) = *(float4*)&As[kk][ty * 8 + 4];
            *(float4*)(b)     = *(float4*)&Bs[kk][tx * 8];
            *(float4*)(b + 4) = *(float4*)&Bs[kk][tx * 8 + 4];
            #pragma unroll
            for (int i = 0; i < 8; i++)
                #pragma unroll
                for (int j = 0; j < 8; j++) acc[i][j] += a[i] * b[j];
        }
        __syncthreads();
    }

    #pragma unroll
    for (int i = 0; i < 8; i++) {
        int row = bm + ty * 8 + i;
        #pragma unroll
        for (int j = 0; j < 8; j++) {
            int col = bn + tx * 8 + j;
            float v = acc[i][j];
            if (bias) v += bias[col];
            if (res)  v += res[(size_t)row * N + col];
            if (relu) v = fmaxf(v, 0.f);
            C[(size_t)row * N + col] = v;
        }
    }
}

// ---------------- fused flash attention ----------------
// Reference computes wei[t,s] = K[t]·Q[s] * scale (row index from K!),
// causal mask s<=t, softmax over s, out[t] = sum_s P[t,s] V[s].
// One block = (b, h, 64-row t-tile). Threads (16,16): thread (tx,ty) owns
// rows t = ty*4+i (i<4) and, per phase, score cols s = tx*4+j or out dims
// d = tx*4+j. Row reductions via width-16 shuffles (one ty = one 16-lane group).
#define FL_STRIDE 68
#define FL_SMEM   (3 * 64 * FL_STRIDE * 4)   // Ks, Vs, QP  (52,224 B -> dynamic)

__global__ __launch_bounds__(256) void flash_kernel(const float* __restrict__ Q,
                                                    const float* __restrict__ Km,
                                                    const float* __restrict__ V,
                                                    float* __restrict__ O) {
    extern __shared__ float sm[];
    float (*Ks)[FL_STRIDE] = (float(*)[FL_STRIDE])sm;                      // [d][t]
    float (*Vs)[FL_STRIDE] = (float(*)[FL_STRIDE])(sm + 64 * FL_STRIDE);   // [s][d]
    float (*QP)[FL_STRIDE] = (float(*)[FL_STRIDE])(sm + 2 * 64 * FL_STRIDE); // Q:[d][s] then P:[s][t]

    const int bt = blockIdx.x;
    const int bh = blockIdx.y, b = bh / HH_, h = bh % HH_;
    const int tx = threadIdx.x, ty = threadIdx.y;
    const int tid = ty * 16 + tx;
    const int lr = tid >> 4;          // 0..15
    const int d4 = (tid & 15) * 4;    // 0..60

    // persist K tile (rows of the score matrix) as [d][t]
    #pragma unroll
    for (int rr = 0; rr < 4; rr++) {
        int r = lr + rr * 16;
        float4 kv = *(const float4*)(Km + (size_t)(b*TT_ + bt*64 + r) * EDIM + h*HD_ + d4);
        Ks[d4+0][r] = kv.x; Ks[d4+1][r] = kv.y; Ks[d4+2][r] = kv.z; Ks[d4+3][r] = kv.w;
    }

    float acc[4][4] = {};
    float m[4], l[4];
    #pragma unroll
    for (int i = 0; i < 4; i++) { m[i] = -1e30f; l[i] = 0.f; }
    const float scale = 0.125f;   // 1/sqrt(64)

    for (int st = 0; st <= bt; st++) {
        __syncthreads();   // prev-iter QP/Vs reads (and initial Ks writes) complete
        #pragma unroll
        for (int rr = 0; rr < 4; rr++) {
            int r = lr + rr * 16;
            float4 qv = *(const float4*)(Q + (size_t)(b*TT_ + st*64 + r) * EDIM + h*HD_ + d4);
            QP[d4+0][r] = qv.x; QP[d4+1][r] = qv.y; QP[d4+2][r] = qv.z; QP[d4+3][r] = qv.w;
            float4 vv = *(const float4*)(V + (size_t)(b*TT_ + st*64 + r) * EDIM + h*HD_ + d4);
            *(float4*)&Vs[r][d4] = vv;
        }
        __syncthreads();

        // S tile: rows t=ty*4+i, cols s=tx*4+j
        float s4[4][4] = {};
        #pragma unroll
        for (int d = 0; d < 64; d++) {
            float4 a = *(float4*)&Ks[d][ty * 4];
            float4 q = *(float4*)&QP[d][tx * 4];
            float ar[4] = {a.x, a.y, a.z, a.w};
            float qr[4] = {q.x, q.y, q.z, q.w};
            #pragma unroll
            for (int i = 0; i < 4; i++)
                #pragma unroll
                for (int j = 0; j < 4; j++) s4[i][j] += ar[i] * qr[j];
        }
        if (st == bt) {
            #pragma unroll
            for (int i = 0; i < 4; i++)
                #pragma unroll
                for (int j = 0; j < 4; j++)
                    s4[i][j] = (tx*4+j <= ty*4+i) ? s4[i][j] * scale : -1e30f;
        } else {
            #pragma unroll
            for (int i = 0; i < 4; i++)
                #pragma unroll
                for (int j = 0; j < 4; j++) s4[i][j] *= scale;
        }

        __syncthreads();   // all Q reads done; QP becomes P:[s][t]

        #pragma unroll
        for (int i = 0; i < 4; i++) {
            float mx = fmaxf(fmaxf(s4[i][0], s4[i][1]), fmaxf(s4[i][2], s4[i][3]));
            #pragma unroll
            for (int o = 8; o; o >>= 1) mx = fmaxf(mx, __shfl_xor_sync(0xffffffffu, mx, o, 16));
            float mn = fmaxf(m[i], mx);
            float alpha = __expf(m[i] - mn);
            float p0 = __expf(s4[i][0] - mn);
            float p1 = __expf(s4[i][1] - mn);
            float p2 = __expf(s4[i][2] - mn);
            float p3 = __expf(s4[i][3] - mn);
            float rs = p0 + p1 + p2 + p3;
            #pragma unroll
            for (int o = 8; o; o >>= 1) rs += __shfl_xor_sync(0xffffffffu, rs, o, 16);
            l[i] = l[i] * alpha + rs;
            m[i] = mn;
            #pragma unroll
            for (int j = 0; j < 4; j++) acc[i][j] *= alpha;
            QP[tx*4+0][ty*4+i] = p0;
            QP[tx*4+1][ty*4+i] = p1;
            QP[tx*4+2][ty*4+i] = p2;
            QP[tx*4+3][ty*4+i] = p3;
        }
        __syncthreads();

        // acc += P @ V : rows t=ty*4+i, cols d=tx*4+j
        #pragma unroll
        for (int s = 0; s < 64; s++) {
            float4 pv = *(float4*)&QP[s][ty * 4];
            float4 vv = *(float4*)&Vs[s][tx * 4];
            float pr[4] = {pv.x, pv.y, pv.z, pv.w};
            float vr[4] = {vv.x, vv.y, vv.z, vv.w};
            #pragma unroll
            for (int i = 0; i < 4; i++)
                #pragma unroll
                for (int j = 0; j < 4; j++) acc[i][j] += pr[i] * vr[j];
        }
    }

    #pragma unroll
    for (int i = 0; i < 4; i++) {
        float inv = 1.f / l[i];
        int tg = bt * 64 + ty * 4 + i;
        #pragma unroll
        for (int j = 0; j < 4; j++)
            O[(size_t)(b*TT_ + tg) * EDIM + h*HD_ + tx*4 + j] = acc[i][j] * inv;
    }
}

// ---------------- host driver ----------------
static float* symAddr(const void* sym) {
    void* p = nullptr;
    cudaGetSymbolAddress(&p, sym);
    return (float*)p;
}

extern "C" void kernel_launch(void* const* d_in, const int* in_sizes, int n_in,
                              void* d_out, int out_size) {
    const void*  tokens = d_in[0];
    const float* emb    = (const float*)d_in[1];
    const float* Wq     = (const float*)d_in[2];
    const float* Wk     = (const float*)d_in[3];
    const float* Wv     = (const float*)d_in[4];
    const float* Wo     = (const float*)d_in[5];
    const float* bo     = (const float*)d_in[6];
    const float* ln1_g  = (const float*)d_in[7];
    const float* ln1_b  = (const float*)d_in[8];
    const float* ln2_g  = (const float*)d_in[9];
    const float* ln2_b  = (const float*)d_in[10];
    const float* W1     = (const float*)d_in[11];
    const float* b1     = (const float*)d_in[12];
    const float* W2     = (const float*)d_in[13];
    const float* b2     = (const float*)d_in[14];
    const float* lnf_g  = (const float*)d_in[15];
    const float* lnf_b  = (const float*)d_in[16];
    const float* Wh     = (const float*)d_in[17];
    const float* bh     = (const float*)d_in[18];

    float* px  = symAddr(g_x);
    float* pz  = symAddr(g_z);
    float* pz2 = symAddr(g_z2);
    float* pq  = symAddr(g_q);
    float* pk  = symAddr(g_k);
    float* pv  = symAddr(g_v);
    float* pat = symAddr(g_attn);
    float* ph  = symAddr(g_h);

    cudaFuncSetAttribute(flash_kernel, cudaFuncAttributeMaxDynamicSharedMemorySize, FL_SMEM);

    detect_kernel<<<1, 256>>>((const int*)tokens);
    embed_kernel<<<MROWS, 256>>>(tokens, emb, px);

    dim3 gEE(EDIM / 128, MROWS / 128);     // (8,16)
    dim3 gEF(FF_ / 128, MROWS / 128);      // (32,16)
    dim3 gEV(VV_ / 128, MROWS / 128);      // (250,16)
    dim3 thr2(16, 16);

    for (int l = 0; l < LL_; l++) {
        ln_kernel<<<MROWS, 256>>>(px, ln1_g + l*EDIM, ln1_b + l*EDIM, pz);
        sgemm_kernel<<<gEE, 256>>>(pz, Wq + (size_t)l*EDIM*EDIM, nullptr, nullptr, pq, MROWS, EDIM, EDIM, 0);
        sgemm_kernel<<<gEE, 256>>>(pz, Wk + (size_t)l*EDIM*EDIM, nullptr, nullptr, pk, MROWS, EDIM, EDIM, 0);
        sgemm_kernel<<<gEE, 256>>>(pz, Wv + (size_t)l*EDIM*EDIM, nullptr, nullptr, pv, MROWS, EDIM, EDIM, 0);
        flash_kernel<<<dim3(TT_/64, BHN), thr2, FL_SMEM>>>(pq, pk, pv, pat);
        sgemm_kernel<<<gEE, 256>>>(pat, Wo + (size_t)l*EDIM*EDIM, bo + l*EDIM, pz, pz, MROWS, EDIM, EDIM, 0);
        ln_kernel<<<MROWS, 256>>>(pz, ln2_g + l*EDIM, ln2_b + l*EDIM, pz2);
        sgemm_kernel<<<gEF, 256>>>(pz2, W1 + (size_t)l*EDIM*FF_, b1 + l*FF_, nullptr, ph, MROWS, FF_, EDIM, 1);
        sgemm_kernel<<<gEE, 256>>>(ph, W2 + (size_t)l*FF_*EDIM, b2 + l*EDIM, pz2, px, MROWS, EDIM, FF_, 0);
    }
    ln_kernel<<<MROWS, 256>>>(px, lnf_g, lnf_b, pz);
    sgemm_kernel<<<gEV, 256>>>(pz, Wh, bh, nullptr, (float*)d_out, MROWS, VV_, EDIM, 0);
}

// round 5
// speedup vs baseline: 2.6985x; 2.6985x over previous
#include <cuda_runtime.h>
#include <cuda_bf16.h>
#include <cstdint>

#define EDIM 1024
#define HD_  64
#define HH_  16
#define TT_  1024
#define BB_  2
#define LL_  4
#define FF_  4096
#define VV_  32000
#define MROWS (BB_*TT_)   // 2048
#define BHN  (BB_*HH_)    // 32

// ---------------- scratch (static device memory; no allocs) ----------------
__device__ float g_x   [MROWS*EDIM];
__device__ float g_z   [MROWS*EDIM];
__device__ float g_z2  [MROWS*EDIM];
__device__ float g_q   [MROWS*EDIM];
__device__ float g_k   [MROWS*EDIM];
__device__ float g_v   [MROWS*EDIM];
__device__ float g_attn[MROWS*EDIM];
__device__ float g_h   [MROWS*FF_];
__device__ int   g_tok64;

// bf16 hi/lo activation buffers (max M x K = 2048 x 4096)
__device__ __nv_bfloat16 g_Ah[MROWS*FF_];
__device__ __nv_bfloat16 g_Al[MROWS*FF_];
// bf16 hi/lo transposed weights [N,K]
__device__ __nv_bfloat16 g_Wqh[LL_*EDIM*EDIM], g_Wql[LL_*EDIM*EDIM];
__device__ __nv_bfloat16 g_Wkh[LL_*EDIM*EDIM], g_Wkl[LL_*EDIM*EDIM];
__device__ __nv_bfloat16 g_Wvh[LL_*EDIM*EDIM], g_Wvl[LL_*EDIM*EDIM];
__device__ __nv_bfloat16 g_Woh[LL_*EDIM*EDIM], g_Wol[LL_*EDIM*EDIM];
__device__ __nv_bfloat16 g_W1h[LL_*EDIM*FF_],  g_W1l[LL_*EDIM*FF_];
__device__ __nv_bfloat16 g_W2h[LL_*EDIM*FF_],  g_W2l[LL_*EDIM*FF_];
__device__ __nv_bfloat16 g_Whh[EDIM*VV_],      g_Whl[EDIM*VV_];

// ---------------- PTX helpers (family-safe: no tcgen05) ----------------
__device__ __forceinline__ uint32_t smem_u32(const void* p) {
    uint32_t a;
    asm("{ .reg .u64 t; cvta.to.shared.u64 t, %1; cvt.u32.u64 %0, t; }" : "=r"(a) : "l"(p));
    return a;
}
__device__ __forceinline__ void ldsm_x4(uint32_t* r, uint32_t addr) {
    asm volatile("ldmatrix.sync.aligned.m8n8.x4.shared.b16 {%0,%1,%2,%3}, [%4];"
                 : "=r"(r[0]), "=r"(r[1]), "=r"(r[2]), "=r"(r[3]) : "r"(addr));
}
__device__ __forceinline__ void mma16816(float* d, const uint32_t* a, const uint32_t* b) {
    asm volatile("mma.sync.aligned.m16n8k16.row.col.f32.bf16.bf16.f32 "
                 "{%0,%1,%2,%3}, {%4,%5,%6,%7}, {%8,%9}, {%0,%1,%2,%3};"
                 : "+f"(d[0]), "+f"(d[1]), "+f"(d[2]), "+f"(d[3])
                 : "r"(a[0]), "r"(a[1]), "r"(a[2]), "r"(a[3]), "r"(b[0]), "r"(b[1]));
}
#define CP_ASYNC16(dst, src) \
    asm volatile("cp.async.cg.shared.global [%0], [%1], 16;" :: "r"(dst), "l"(src))
#define CP_COMMIT() asm volatile("cp.async.commit_group;" ::: "memory")
#define CP_WAIT(n)  asm volatile("cp.async.wait_group %0;" :: "n"(n) : "memory")

// ---------------- reductions ----------------
__device__ __forceinline__ float blockReduceSum(float v, float* sh) {
    __syncthreads();
    #pragma unroll
    for (int o = 16; o; o >>= 1) v += __shfl_xor_sync(0xffffffffu, v, o);
    if ((threadIdx.x & 31) == 0) sh[threadIdx.x >> 5] = v;
    __syncthreads();
    int nw = blockDim.x >> 5;
    float t = (threadIdx.x < (unsigned)nw) ? sh[threadIdx.x] : 0.f;
    if (threadIdx.x < 32) {
        #pragma unroll
        for (int o = 16; o; o >>= 1) t += __shfl_xor_sync(0xffffffffu, t, o);
        if (threadIdx.x == 0) sh[0] = t;
    }
    __syncthreads();
    return sh[0];
}

// ---------------- token dtype detect ----------------
__global__ void detect_kernel(const int* __restrict__ tok) {
    __shared__ int nz;
    if (threadIdx.x == 0) nz = 0;
    __syncthreads();
    int c = 0;
    for (int j = threadIdx.x; j < 1024; j += blockDim.x)
        if (tok[2*j + 1] != 0) c++;
    if (c) atomicAdd(&nz, c);
    __syncthreads();
    if (threadIdx.x == 0) g_tok64 = (nz == 0) ? 1 : 0;
}

// ---------------- embedding + positional encoding ----------------
__global__ __launch_bounds__(256) void embed_kernel(const void* __restrict__ tokp,
                                                    const float* __restrict__ emb,
                                                    float* __restrict__ X) {
    int row = blockIdx.x;
    int t   = row & (TT_ - 1);
    int token;
    if (g_tok64) token = (int)((const long long*)tokp)[row];
    else         token = ((const int*)tokp)[row];
    int e = threadIdx.x * 4;
    float4 v = *(const float4*)(emb + (size_t)token * EDIM + e);
    double i0 = (double)(e >> 1);
    double i1 = i0 + 1.0;
    double d0 = pow(10000.0, 2.0 * i0 / (double)EDIM);
    double d1 = pow(10000.0, 2.0 * i1 / (double)EDIM);
    double a0 = (double)t / d0;
    double a1 = (double)t / d1;
    v.x += (float)sin(a0); v.y += (float)cos(a0);
    v.z += (float)sin(a1); v.w += (float)cos(a1);
    *(float4*)(X + (size_t)row * EDIM + e) = v;
}

// ---------------- layernorm ----------------
__global__ __launch_bounds__(256) void ln_kernel(const float* __restrict__ X,
                                                 const float* __restrict__ g,
                                                 const float* __restrict__ b,
                                                 float* __restrict__ Y) {
    __shared__ float sh[32];
    int row = blockIdx.x;
    int e = threadIdx.x * 4;
    const float* xr = X + (size_t)row * EDIM;
    float4 v = *(const float4*)(xr + e);
    float mean = blockReduceSum(v.x + v.y + v.z + v.w, sh) * (1.f / EDIM);
    float dx = v.x - mean, dy = v.y - mean, dz = v.z - mean, dw = v.w - mean;
    float var = blockReduceSum(dx*dx + dy*dy + dz*dz + dw*dw, sh) * (1.f / EDIM);
    float r = rsqrtf(var + 1e-5f);
    float4 gg = *(const float4*)(g + e);
    float4 bb = *(const float4*)(b + e);
    float4 o;
    o.x = dx * r * gg.x + bb.x;
    o.y = dy * r * gg.y + bb.y;
    o.z = dz * r * gg.z + bb.z;
    o.w = dw * r * gg.w + bb.w;
    *(float4*)(Y + (size_t)row * EDIM + e) = o;
}

// ---------------- fp32 -> bf16 hi/lo split (activations) ----------------
__global__ __launch_bounds__(256) void cvt_act_kernel(const float* __restrict__ A,
                                                      __nv_bfloat16* __restrict__ H,
                                                      __nv_bfloat16* __restrict__ Lo) {
    size_t i = ((size_t)blockIdx.x * 256 + threadIdx.x) * 4;
    float4 a = *(const float4*)(A + i);
    __nv_bfloat16 h0 = __float2bfloat16(a.x), h1 = __float2bfloat16(a.y);
    __nv_bfloat16 h2 = __float2bfloat16(a.z), h3 = __float2bfloat16(a.w);
    __nv_bfloat162 hp0; hp0.x = h0; hp0.y = h1;
    __nv_bfloat162 hp1; hp1.x = h2; hp1.y = h3;
    __nv_bfloat162 lp0, lp1;
    lp0.x = __float2bfloat16(a.x - __bfloat162float(h0));
    lp0.y = __float2bfloat16(a.y - __bfloat162float(h1));
    lp1.x = __float2bfloat16(a.z - __bfloat162float(h2));
    lp1.y = __float2bfloat16(a.w - __bfloat162float(h3));
    *(__nv_bfloat162*)(H + i)      = hp0;
    *(__nv_bfloat162*)(H + i + 2)  = hp1;
    *(__nv_bfloat162*)(Lo + i)     = lp0;
    *(__nv_bfloat162*)(Lo + i + 2) = lp1;
}

// ---------------- fp32 W[K,N] -> bf16 hi/lo transposed [N,K] ----------------
__global__ __launch_bounds__(256) void cvt_wT_kernel(const float* __restrict__ W,
                                                     __nv_bfloat16* __restrict__ H,
                                                     __nv_bfloat16* __restrict__ Lo,
                                                     int K, int N) {
    __shared__ float t[32][33];
    int n0 = blockIdx.x * 32, k0 = blockIdx.y * 32;
    int tx = threadIdx.x & 31, ty = threadIdx.x >> 5;   // ty 0..7
    #pragma unroll
    for (int r = 0; r < 4; r++)
        t[ty + r*8][tx] = W[(size_t)(k0 + ty + r*8) * N + n0 + tx];
    __syncthreads();
    #pragma unroll
    for (int r = 0; r < 4; r++) {
        float v = t[tx][ty + r*8];                     // W[k0+tx][n0+ty+r*8]
        __nv_bfloat16 h = __float2bfloat16(v);
        __nv_bfloat16 l = __float2bfloat16(v - __bfloat162float(h));
        size_t o = (size_t)(n0 + ty + r*8) * K + k0 + tx;
        H[o] = h; Lo[o] = l;
    }
}

// ---------------- bf16 hi/lo tensor-core GEMM (mma.sync path) ----------------
// C[M,N] = A[M,K] @ B[N,K]^T  with A,B split hi/lo; fp32 accum of hh+hl+lh.
// CTA tile 128x128, 8 warps 2(m)x4(n), warp tile 64x32. K chunk = 32.
// smem: per stage 4 tiles (Ah,Al,Bh,Bl) of [128][40] bf16 (pad for ldmatrix).
#define TSTRIDE 40
#define TILE_ELEMS (128 * TSTRIDE)          // bf16 per tile
#define STAGE_ELEMS (4 * TILE_ELEMS)        // 20480 bf16
#define GEMM_SMEM (2 * STAGE_ELEMS * 2)     // 81920 bytes

__global__ __launch_bounds__(256) void gemm_kernel(
    const __nv_bfloat16* __restrict__ Ah, const __nv_bfloat16* __restrict__ Al,
    const __nv_bfloat16* __restrict__ Bh0, const __nv_bfloat16* __restrict__ Bl0,
    const __nv_bfloat16* __restrict__ Bh1, const __nv_bfloat16* __restrict__ Bl1,
    const __nv_bfloat16* __restrict__ Bh2, const __nv_bfloat16* __restrict__ Bl2,
    float* __restrict__ C0, float* __restrict__ C1, float* __restrict__ C2,
    const float* __restrict__ bias, const float* __restrict__ res,
    int K, int N, int relu)
{
    extern __shared__ __nv_bfloat16 smem[];
    const int tid = threadIdx.x;
    const int lane = tid & 31, wid = tid >> 5;
    const int wm = wid & 1, wn = wid >> 1;
    const int bm = blockIdx.y * 128, bn = blockIdx.x * 128;
    const int z = blockIdx.z;
    const __nv_bfloat16* Bh = (z == 0) ? Bh0 : (z == 1) ? Bh1 : Bh2;
    const __nv_bfloat16* Bl = (z == 0) ? Bl0 : (z == 1) ? Bl1 : Bl2;
    float* C = (z == 0) ? C0 : (z == 1) ? C1 : C2;

    const uint32_t sb = smem_u32(smem);
    const int nc = K >> 5;

    // cp.async loader: 4 tiles x 512 chunks(16B); thread does 2 chunks/tile
    const int c_row = tid >> 2;          // chunk/4 for chunk=tid
    const int c_cc  = (tid & 3) * 8;     // bf16 col offset of 16B chunk
    const int c_row2 = (tid + 256) >> 2;
    const int c_cc2  = ((tid + 256) & 3) * 8;

    auto load_stage = [&](int st, int kc) {
        const __nv_bfloat16* srcs[4] = {Ah, Al, Bh, Bl};
        #pragma unroll
        for (int tile = 0; tile < 4; tile++) {
            const __nv_bfloat16* src = srcs[tile];
            const int rb = (tile < 2) ? bm : bn;
            uint32_t dstb = sb + (uint32_t)((st * STAGE_ELEMS + tile * TILE_ELEMS) * 2);
            const __nv_bfloat16* s1 = src + (size_t)(rb + c_row) * K + kc * 32 + c_cc;
            const __nv_bfloat16* s2 = src + (size_t)(rb + c_row2) * K + kc * 32 + c_cc2;
            CP_ASYNC16(dstb + (c_row * TSTRIDE + c_cc) * 2, s1);
            CP_ASYNC16(dstb + (c_row2 * TSTRIDE + c_cc2) * 2, s2);
        }
    };

    float acc[4][4][4];
    #pragma unroll
    for (int i = 0; i < 4; i++)
        #pragma unroll
        for (int j = 0; j < 4; j++)
            #pragma unroll
            for (int r = 0; r < 4; r++) acc[i][j][r] = 0.f;

    load_stage(0, 0);
    CP_COMMIT();

    // ldmatrix lane addressing
    const int a_lrow = lane & 15;                 // + mrow0
    const int a_lcol = (lane & 16) ? 8 : 0;       // + k0
    const int b_lrow = (lane & 7) + ((lane & 16) ? 8 : 0);  // + n0
    const int b_lcol = (lane & 8) ? 8 : 0;        // + k0

    for (int c = 0; c < nc; c++) {
        if (c + 1 < nc) { load_stage((c + 1) & 1, c + 1); CP_COMMIT(); CP_WAIT(1); }
        else            { CP_WAIT(0); }
        __syncthreads();

        const uint32_t stb = sb + (uint32_t)(((c & 1) * STAGE_ELEMS) * 2);
        const uint32_t pAh = stb;
        const uint32_t pAl = stb + TILE_ELEMS * 2;
        const uint32_t pBh = stb + 2 * TILE_ELEMS * 2;
        const uint32_t pBl = stb + 3 * TILE_ELEMS * 2;

        #pragma unroll
        for (int ks = 0; ks < 2; ks++) {
            const int k0 = ks * 16;
            uint32_t ah[4][4], al[4][4];
            #pragma unroll
            for (int mf = 0; mf < 4; mf++) {
                int row = wm * 64 + mf * 16 + a_lrow;
                uint32_t off = (uint32_t)((row * TSTRIDE + k0 + a_lcol) * 2);
                ldsm_x4(ah[mf], pAh + off);
                ldsm_x4(al[mf], pAl + off);
            }
            uint32_t bh[2][4], bl[2][4];
            #pragma unroll
            for (int np = 0; np < 2; np++) {
                int rown = wn * 32 + np * 16 + b_lrow;
                uint32_t off = (uint32_t)((rown * TSTRIDE + k0 + b_lcol) * 2);
                ldsm_x4(bh[np], pBh + off);
                ldsm_x4(bl[np], pBl + off);
            }
            #pragma unroll
            for (int mf = 0; mf < 4; mf++)
                #pragma unroll
                for (int np = 0; np < 2; np++)
                    #pragma unroll
                    for (int sub = 0; sub < 2; sub++) {
                        int nf = np * 2 + sub;
                        mma16816(acc[mf][nf], ah[mf], &bh[np][2 * sub]);
                        mma16816(acc[mf][nf], ah[mf], &bl[np][2 * sub]);
                        mma16816(acc[mf][nf], al[mf], &bh[np][2 * sub]);
                    }
        }
        __syncthreads();
    }

    // epilogue
    #pragma unroll
    for (int mf = 0; mf < 4; mf++) {
        int row0 = bm + wm * 64 + mf * 16 + (lane >> 2);
        #pragma unroll
        for (int nf = 0; nf < 4; nf++) {
            int col0 = bn + wn * 32 + nf * 8 + (lane & 3) * 2;
            #pragma unroll
            for (int r = 0; r < 4; r++) {
                int row = row0 + ((r >> 1) ? 8 : 0);
                int col = col0 + (r & 1);
                float v = acc[mf][nf][r];
                if (bias) v += bias[col];
                if (res)  v += res[(size_t)row * N + col];
                if (relu) v = fmaxf(v, 0.f);
                C[(size_t)row * N + col] = v;
            }
        }
    }
}

// ---------------- fused flash attention (fp32, from R3 pass) ----------------
#define FL_STRIDE 68
#define FL_SMEM   (3 * 64 * FL_STRIDE * 4)

__global__ __launch_bounds__(256) void flash_kernel(const float* __restrict__ Q,
                                                    const float* __restrict__ Km,
                                                    const float* __restrict__ V,
                                                    float* __restrict__ O) {
    extern __shared__ float smf[];
    float (*Ks)[FL_STRIDE] = (float(*)[FL_STRIDE])smf;
    float (*Vs)[FL_STRIDE] = (float(*)[FL_STRIDE])(smf + 64 * FL_STRIDE);
    float (*QP)[FL_STRIDE] = (float(*)[FL_STRIDE])(smf + 2 * 64 * FL_STRIDE);

    const int bt = blockIdx.x;
    const int bh = blockIdx.y, b = bh / HH_, h = bh % HH_;
    const int tx = threadIdx.x, ty = threadIdx.y;
    const int tid = ty * 16 + tx;
    const int lr = tid >> 4;
    const int d4 = (tid & 15) * 4;

    #pragma unroll
    for (int rr = 0; rr < 4; rr++) {
        int r = lr + rr * 16;
        float4 kv = *(const float4*)(Km + (size_t)(b*TT_ + bt*64 + r) * EDIM + h*HD_ + d4);
        Ks[d4+0][r] = kv.x; Ks[d4+1][r] = kv.y; Ks[d4+2][r] = kv.z; Ks[d4+3][r] = kv.w;
    }

    float acc[4][4] = {};
    float m[4], l[4];
    #pragma unroll
    for (int i = 0; i < 4; i++) { m[i] = -1e30f; l[i] = 0.f; }
    const float scale = 0.125f;

    for (int st = 0; st <= bt; st++) {
        __syncthreads();
        #pragma unroll
        for (int rr = 0; rr < 4; rr++) {
            int r = lr + rr * 16;
            float4 qv = *(const float4*)(Q + (size_t)(b*TT_ + st*64 + r) * EDIM + h*HD_ + d4);
            QP[d4+0][r] = qv.x; QP[d4+1][r] = qv.y; QP[d4+2][r] = qv.z; QP[d4+3][r] = qv.w;
            float4 vv = *(const float4*)(V + (size_t)(b*TT_ + st*64 + r) * EDIM + h*HD_ + d4);
            *(float4*)&Vs[r][d4] = vv;
        }
        __syncthreads();

        float s4[4][4] = {};
        #pragma unroll
        for (int d = 0; d < 64; d++) {
            float4 a = *(float4*)&Ks[d][ty * 4];
            float4 q = *(float4*)&QP[d][tx * 4];
            float ar[4] = {a.x, a.y, a.z, a.w};
            float qr[4] = {q.x, q.y, q.z, q.w};
            #pragma unroll
            for (int i = 0; i < 4; i++)
                #pragma unroll
                for (int j = 0; j < 4; j++) s4[i][j] += ar[i] * qr[j];
        }
        if (st == bt) {
            #pragma unroll
            for (int i = 0; i < 4; i++)
                #pragma unroll
                for (int j = 0; j < 4; j++)
                    s4[i][j] = (tx*4+j <= ty*4+i) ? s4[i][j] * scale : -1e30f;
        } else {
            #pragma unroll
            for (int i = 0; i < 4; i++)
                #pragma unroll
                for (int j = 0; j < 4; j++) s4[i][j] *= scale;
        }

        __syncthreads();

        #pragma unroll
        for (int i = 0; i < 4; i++) {
            float mx = fmaxf(fmaxf(s4[i][0], s4[i][1]), fmaxf(s4[i][2], s4[i][3]));
            #pragma unroll
            for (int o = 8; o; o >>= 1) mx = fmaxf(mx, __shfl_xor_sync(0xffffffffu, mx, o, 16));
            float mn = fmaxf(m[i], mx);
            float alpha = __expf(m[i] - mn);
            float p0 = __expf(s4[i][0] - mn);
            float p1 = __expf(s4[i][1] - mn);
            float p2 = __expf(s4[i][2] - mn);
            float p3 = __expf(s4[i][3] - mn);
            float rs = p0 + p1 + p2 + p3;
            #pragma unroll
            for (int o = 8; o; o >>= 1) rs += __shfl_xor_sync(0xffffffffu, rs, o, 16);
            l[i] = l[i] * alpha + rs;
            m[i] = mn;
            #pragma unroll
            for (int j = 0; j < 4; j++) acc[i][j] *= alpha;
            QP[tx*4+0][ty*4+i] = p0;
            QP[tx*4+1][ty*4+i] = p1;
            QP[tx*4+2][ty*4+i] = p2;
            QP[tx*4+3][ty*4+i] = p3;
        }
        __syncthreads();

        #pragma unroll
        for (int s = 0; s < 64; s++) {
            float4 pv = *(float4*)&QP[s][ty * 4];
            float4 vv = *(float4*)&Vs[s][tx * 4];
            float pr[4] = {pv.x, pv.y, pv.z, pv.w};
            float vr[4] = {vv.x, vv.y, vv.z, vv.w};
            #pragma unroll
            for (int i = 0; i < 4; i++)
                #pragma unroll
                for (int j = 0; j < 4; j++) acc[i][j] += pr[i] * vr[j];
        }
    }

    #pragma unroll
    for (int i = 0; i < 4; i++) {
        float inv = 1.f / l[i];
        int tg = bt * 64 + ty * 4 + i;
        #pragma unroll
        for (int j = 0; j < 4; j++)
            O[(size_t)(b*TT_ + tg) * EDIM + h*HD_ + tx*4 + j] = acc[i][j] * inv;
    }
}

// ---------------- host driver ----------------
template <typename T>
static T* symAddr(const void* sym) {
    void* p = nullptr;
    cudaGetSymbolAddress(&p, sym);
    return (T*)p;
}

extern "C" void kernel_launch(void* const* d_in, const int* in_sizes, int n_in,
                              void* d_out, int out_size) {
    const void*  tokens = d_in[0];
    const float* emb    = (const float*)d_in[1];
    const float* Wq     = (const float*)d_in[2];
    const float* Wk     = (const float*)d_in[3];
    const float* Wv     = (const float*)d_in[4];
    const float* Wo     = (const float*)d_in[5];
    const float* bo     = (const float*)d_in[6];
    const float* ln1_g  = (const float*)d_in[7];
    const float* ln1_b  = (const float*)d_in[8];
    const float* ln2_g  = (const float*)d_in[9];
    const float* ln2_b  = (const float*)d_in[10];
    const float* W1     = (const float*)d_in[11];
    const float* b1     = (const float*)d_in[12];
    const float* W2     = (const float*)d_in[13];
    const float* b2     = (const float*)d_in[14];
    const float* lnf_g  = (const float*)d_in[15];
    const float* lnf_b  = (const float*)d_in[16];
    const float* Wh     = (const float*)d_in[17];
    const float* bh     = (const float*)d_in[18];

    float* px  = symAddr<float>(g_x);
    float* pz  = symAddr<float>(g_z);
    float* pz2 = symAddr<float>(g_z2);
    float* pq  = symAddr<float>(g_q);
    float* pk  = symAddr<float>(g_k);
    float* pv  = symAddr<float>(g_v);
    float* pat = symAddr<float>(g_attn);
    float* ph  = symAddr<float>(g_h);
    __nv_bfloat16* pAh = symAddr<__nv_bfloat16>(g_Ah);
    __nv_bfloat16* pAl = symAddr<__nv_bfloat16>(g_Al);
    __nv_bfloat16* pWqh = symAddr<__nv_bfloat16>(g_Wqh), *pWql = symAddr<__nv_bfloat16>(g_Wql);
    __nv_bfloat16* pWkh = symAddr<__nv_bfloat16>(g_Wkh), *pWkl = symAddr<__nv_bfloat16>(g_Wkl);
    __nv_bfloat16* pWvh = symAddr<__nv_bfloat16>(g_Wvh), *pWvl = symAddr<__nv_bfloat16>(g_Wvl);
    __nv_bfloat16* pWoh = symAddr<__nv_bfloat16>(g_Woh), *pWol = symAddr<__nv_bfloat16>(g_Wol);
    __nv_bfloat16* pW1h = symAddr<__nv_bfloat16>(g_W1h), *pW1l = symAddr<__nv_bfloat16>(g_W1l);
    __nv_bfloat16* pW2h = symAddr<__nv_bfloat16>(g_W2h), *pW2l = symAddr<__nv_bfloat16>(g_W2l);
    __nv_bfloat16* pWhh = symAddr<__nv_bfloat16>(g_Whh), *pWhl = symAddr<__nv_bfloat16>(g_Whl);

    cudaFuncSetAttribute(flash_kernel, cudaFuncAttributeMaxDynamicSharedMemorySize, FL_SMEM);
    cudaFuncSetAttribute(gemm_kernel,  cudaFuncAttributeMaxDynamicSharedMemorySize, GEMM_SMEM);

    const size_t EE = (size_t)EDIM * EDIM;
    const size_t EF = (size_t)EDIM * FF_;

    // ---- weight conversion (transpose + bf16 split) ----
    dim3 cEE(EDIM/32, EDIM/32);
    dim3 cEF(FF_/32, EDIM/32);
    dim3 cFE(EDIM/32, FF_/32);
    dim3 cEV(VV_/32, EDIM/32);
    for (int l = 0; l < LL_; l++) {
        cvt_wT_kernel<<<cEE, 256>>>(Wq + l*EE, pWqh + l*EE, pWql + l*EE, EDIM, EDIM);
        cvt_wT_kernel<<<cEE, 256>>>(Wk + l*EE, pWkh + l*EE, pWkl + l*EE, EDIM, EDIM);
        cvt_wT_kernel<<<cEE, 256>>>(Wv + l*EE, pWvh + l*EE, pWvl + l*EE, EDIM, EDIM);
        cvt_wT_kernel<<<cEE, 256>>>(Wo + l*EE, pWoh + l*EE, pWol + l*EE, EDIM, EDIM);
        cvt_wT_kernel<<<cEF, 256>>>(W1 + l*EF, pW1h + l*EF, pW1l + l*EF, EDIM, FF_);
        cvt_wT_kernel<<<cFE, 256>>>(W2 + l*EF, pW2h + l*EF, pW2l + l*EF, FF_, EDIM);
    }
    cvt_wT_kernel<<<cEV, 256>>>(Wh, pWhh, pWhl, EDIM, VV_);

    detect_kernel<<<1, 256>>>((const int*)tokens);
    embed_kernel<<<MROWS, 256>>>(tokens, emb, px);

    dim3 gQKV(EDIM/128, MROWS/128, 3);
    dim3 gEE(EDIM/128, MROWS/128, 1);
    dim3 gEF(FF_/128, MROWS/128, 1);
    dim3 gEV(VV_/128, MROWS/128, 1);
    dim3 thr2(16, 16);
    const int nZ = MROWS * EDIM / 1024;
    const int nH = MROWS * FF_  / 1024;

    for (int l = 0; l < LL_; l++) {
        ln_kernel<<<MROWS, 256>>>(px, ln1_g + l*EDIM, ln1_b + l*EDIM, pz);
        cvt_act_kernel<<<nZ, 256>>>(pz, pAh, pAl);
        gemm_kernel<<<gQKV, 256, GEMM_SMEM>>>(pAh, pAl,
            pWqh + l*EE, pWql + l*EE, pWkh + l*EE, pWkl + l*EE, pWvh + l*EE, pWvl + l*EE,
            pq, pk, pv, nullptr, nullptr, EDIM, EDIM, 0);
        flash_kernel<<<dim3(TT_/64, BHN), thr2, FL_SMEM>>>(pq, pk, pv, pat);
        cvt_act_kernel<<<nZ, 256>>>(pat, pAh, pAl);
        gemm_kernel<<<gEE, 256, GEMM_SMEM>>>(pAh, pAl,
            pWoh + l*EE, pWol + l*EE, nullptr, nullptr, nullptr, nullptr,
            pz, nullptr, nullptr, bo + l*EDIM, pz, EDIM, EDIM, 0);
        ln_kernel<<<MROWS, 256>>>(pz, ln2_g + l*EDIM, ln2_b + l*EDIM, pz2);
        cvt_act_kernel<<<nZ, 256>>>(pz2, pAh, pAl);
        gemm_kernel<<<gEF, 256, GEMM_SMEM>>>(pAh, pAl,
            pW1h + l*EF, pW1l + l*EF, nullptr, nullptr, nullptr, nullptr,
            ph, nullptr, nullptr, b1 + l*FF_, nullptr, EDIM, FF_, 1);
        cvt_act_kernel<<<nH, 256>>>(ph, pAh, pAl);
        gemm_kernel<<<gEE, 256, GEMM_SMEM>>>(pAh, pAl,
            pW2h + l*EF, pW2l + l*EF, nullptr, nullptr, nullptr, nullptr,
            px, nullptr, nullptr, b2 + l*EDIM, pz2, FF_, EDIM, 0);
    }
    ln_kernel<<<MROWS, 256>>>(px, lnf_g, lnf_b, pz);
    cvt_act_kernel<<<nZ, 256>>>(pz, pAh, pAl);
    gemm_kernel<<<gEV, 256, GEMM_SMEM>>>(pAh, pAl,
        pWhh, pWhl, nullptr, nullptr, nullptr, nullptr,
        (float*)d_out, nullptr, nullptr, bh, nullptr, EDIM, VV_, 0);
}